// round 15
// baseline (speedup 1.0000x reference)
#include <cuda_runtime.h>
#include <cstdint>

#define NNODES 100000
#define NEDGES 1600000
#define F_IN   128
#define HID    64
#define HID4   (HID / 4)

#define SCAN_T 1024
#define NSCANB ((NNODES + SCAN_T - 1) / SCAN_T)   // 98

__device__ float  g_dinv[NNODES];
__device__ float4 g_bufA[(size_t)NNODES * HID4];
__device__ float4 g_bufB[(size_t)NNODES * HID4];
__device__ int    g_degi  [NNODES];
__device__ int    g_cursor[NNODES];
__device__ int    g_rowptr[NNODES + 1];
__device__ int    g_bsum  [NSCANB];
__device__ int    g_csrc  [NEDGES];

// ---------------------------------------------------------------------------
// tf32 + cp.async helpers
// ---------------------------------------------------------------------------
__device__ __forceinline__ uint32_t f2tf32(float x) {
    uint32_t r;
    asm("cvt.rna.tf32.f32 %0, %1;" : "=r"(r) : "f"(x));
    return r;
}
__device__ __forceinline__ void mma_tf32(float* d, const uint32_t* a,
                                         const uint32_t* b) {
    asm("mma.sync.aligned.m16n8k8.row.col.f32.tf32.tf32.f32 "
        "{%0,%1,%2,%3}, {%4,%5,%6,%7}, {%8,%9}, {%0,%1,%2,%3};"
        : "+f"(d[0]), "+f"(d[1]), "+f"(d[2]), "+f"(d[3])
        : "r"(a[0]), "r"(a[1]), "r"(a[2]), "r"(a[3]), "r"(b[0]), "r"(b[1]));
}
__device__ __forceinline__ void split_tf32(float x, uint32_t& hi, uint32_t& lo) {
    hi = f2tf32(x);
    lo = f2tf32(x - __uint_as_float(hi));
}
__device__ __forceinline__ void cp_async16(void* smem_dst, const void* gsrc,
                                           int src_bytes) {
    uint32_t d = (uint32_t)__cvta_generic_to_shared(smem_dst);
    asm volatile("cp.async.ca.shared.global [%0], [%1], 16, %2;"
                 :: "r"(d), "l"(gsrc), "r"(src_bytes) : "memory");
}
__device__ __forceinline__ void cp_commit() {
    asm volatile("cp.async.commit_group;" ::: "memory");
}
template <int N>
__device__ __forceinline__ void cp_wait() {
    asm volatile("cp.async.wait_group %0;" :: "n"(N) : "memory");
}

// ---------------------------------------------------------------------------
// CSR construction
// ---------------------------------------------------------------------------
__global__ void k_zero() {
    int v = blockIdx.x * blockDim.x + threadIdx.x;
    if (v < NNODES) { g_degi[v] = 0; g_cursor[v] = 0; }
}

__global__ void k_count(const int* __restrict__ ei) {
    int e = blockIdx.x * blockDim.x + threadIdx.x;
    if (e < NEDGES) atomicAdd(&g_degi[ei[NEDGES + e]], 1);
}

__global__ __launch_bounds__(SCAN_T) void k_scan1() {
    __shared__ int s[SCAN_T];
    int i = blockIdx.x * SCAN_T + threadIdx.x;
    int v = (i < NNODES) ? g_degi[i] : 0;
    s[threadIdx.x] = v;
    __syncthreads();
    for (int off = 1; off < SCAN_T; off <<= 1) {
        int t = (threadIdx.x >= off) ? s[threadIdx.x - off] : 0;
        __syncthreads();
        s[threadIdx.x] += t;
        __syncthreads();
    }
    if (i < NNODES) g_rowptr[i] = s[threadIdx.x] - v;
    if (threadIdx.x == SCAN_T - 1) g_bsum[blockIdx.x] = s[SCAN_T - 1];
}

__global__ __launch_bounds__(SCAN_T) void k_scan23() {
    __shared__ int sp[128];
    int t = threadIdx.x;
    if (t < 128) sp[t] = (t < blockIdx.x && t < NSCANB) ? g_bsum[t] : 0;
    __syncthreads();
    for (int off = 64; off > 0; off >>= 1) {
        if (t < off) sp[t] += sp[t + off];
        __syncthreads();
    }
    int prefix = sp[0];
    int i = blockIdx.x * SCAN_T + t;
    if (i < NNODES) {
        g_rowptr[i] += prefix;
        g_dinv[i] = rsqrtf((float)(g_degi[i] + 1));
    }
    if (blockIdx.x == 0 && t == 0) g_rowptr[NNODES] = NEDGES;
}

__global__ void k_fill(const int* __restrict__ ei) {
    int e = blockIdx.x * blockDim.x + threadIdx.x;
    if (e < NEDGES) {
        int s = ei[e];
        int d = ei[NEDGES + e];
        int pos = g_rowptr[d] + atomicAdd(&g_cursor[d], 1);
        g_csrc[pos] = s;
    }
}

// ---------------------------------------------------------------------------
// K3: GEMM1  bufA = (x @ W1) * dinv[row]   -- 3xTF32 + cp.async pipeline
//   Raw x chunks double-buffered via LDGSTS; hi/lo split in a convert phase.
// ---------------------------------------------------------------------------
__global__ __launch_bounds__(256) void k_gemm1(const float* __restrict__ x,
                                               const float* __restrict__ W1) {
    __shared__ float    sAraw[2][128][16];               // 16 KB raw double-buf
    __shared__ uint32_t sAhi[128][20], sAlo[128][20];    // 20.5 KB
    __shared__ uint32_t sBhi[16][72],  sBlo[16][72];     // 9.2 KB

    const int m0   = blockIdx.x * 128;
    const int tid  = threadIdx.x;
    const int wid  = tid >> 5;
    const int lane = tid & 31;
    const int g    = lane >> 2;
    const int tg   = lane & 3;
    const int wm   = (wid >> 1) * 32;
    const int wn   = (wid & 1) * 32;

    float acc[2][4][4];
#pragma unroll
    for (int mt = 0; mt < 2; mt++)
#pragma unroll
        for (int nt = 0; nt < 4; nt++)
#pragma unroll
            for (int c = 0; c < 4; c++) acc[mt][nt][c] = 0.f;

    // issue chunk 0
    {
#pragma unroll
        for (int l = 0; l < 2; l++) {
            int idx = tid + l * 256;
            int r = idx >> 2, c4 = idx & 3;
            int row = m0 + r;
            int rr = row < NNODES ? row : NNODES - 1;
            cp_async16(&sAraw[0][r][c4 * 4],
                       x + (size_t)rr * F_IN + c4 * 4,
                       row < NNODES ? 16 : 0);
        }
        cp_commit();
    }

#pragma unroll 1
    for (int kc = 0; kc < 8; kc++) {
        if (kc < 7) {
#pragma unroll
            for (int l = 0; l < 2; l++) {
                int idx = tid + l * 256;
                int r = idx >> 2, c4 = idx & 3;
                int row = m0 + r;
                int rr = row < NNODES ? row : NNODES - 1;
                cp_async16(&sAraw[(kc + 1) & 1][r][c4 * 4],
                           x + (size_t)rr * F_IN + (kc + 1) * 16 + c4 * 4,
                           row < NNODES ? 16 : 0);
            }
            cp_commit();
            cp_wait<1>();
        } else {
            cp_wait<0>();
        }
        __syncthreads();   // raw[kc] ready; previous compute done

        // convert phase: raw -> hi/lo split
#pragma unroll
        for (int l = 0; l < 2; l++) {
            int idx = tid + l * 256;
            int r = idx >> 2, c4 = idx & 3;
            float4 v = *(const float4*)&sAraw[kc & 1][r][c4 * 4];
            uint4 h, lo;
            split_tf32(v.x, h.x, lo.x);
            split_tf32(v.y, h.y, lo.y);
            split_tf32(v.z, h.z, lo.z);
            split_tf32(v.w, h.w, lo.w);
            *(uint4*)&sAhi[r][c4 * 4] = h;
            *(uint4*)&sAlo[r][c4 * 4] = lo;
        }
        // W chunk (small, L2-cached): load + split
        {
            int k = tid >> 4, c4 = tid & 15;
            float4 v = __ldg((const float4*)(W1 + (size_t)(kc * 16 + k) * HID) + c4);
            uint4 h, lo;
            split_tf32(v.x, h.x, lo.x);
            split_tf32(v.y, h.y, lo.y);
            split_tf32(v.z, h.z, lo.z);
            split_tf32(v.w, h.w, lo.w);
            *(uint4*)&sBhi[k][c4 * 4] = h;
            *(uint4*)&sBlo[k][c4 * 4] = lo;
        }
        __syncthreads();

#pragma unroll
        for (int s = 0; s < 2; s++) {
            int k0 = s * 8;
            uint32_t ahi[2][4], alo[2][4], bhi[4][2], blo[4][2];
#pragma unroll
            for (int mt = 0; mt < 2; mt++) {
                int r = wm + mt * 16 + g;
                ahi[mt][0] = sAhi[r    ][k0 + tg];
                ahi[mt][1] = sAhi[r + 8][k0 + tg];
                ahi[mt][2] = sAhi[r    ][k0 + tg + 4];
                ahi[mt][3] = sAhi[r + 8][k0 + tg + 4];
                alo[mt][0] = sAlo[r    ][k0 + tg];
                alo[mt][1] = sAlo[r + 8][k0 + tg];
                alo[mt][2] = sAlo[r    ][k0 + tg + 4];
                alo[mt][3] = sAlo[r + 8][k0 + tg + 4];
            }
#pragma unroll
            for (int nt = 0; nt < 4; nt++) {
                int n = wn + nt * 8 + g;
                bhi[nt][0] = sBhi[k0 + tg    ][n];
                bhi[nt][1] = sBhi[k0 + tg + 4][n];
                blo[nt][0] = sBlo[k0 + tg    ][n];
                blo[nt][1] = sBlo[k0 + tg + 4][n];
            }
#pragma unroll
            for (int mt = 0; mt < 2; mt++)
#pragma unroll
                for (int nt = 0; nt < 4; nt++) {
                    mma_tf32(acc[mt][nt], ahi[mt], bhi[nt]);
                    mma_tf32(acc[mt][nt], ahi[mt], blo[nt]);
                    mma_tf32(acc[mt][nt], alo[mt], bhi[nt]);
                }
        }
        __syncthreads();
    }

    float2* outp = (float2*)g_bufA;
#pragma unroll
    for (int mt = 0; mt < 2; mt++) {
        int r0 = m0 + wm + mt * 16 + g;
        int r1 = r0 + 8;
        float dv0 = (r0 < NNODES) ? g_dinv[r0] : 0.f;
        float dv1 = (r1 < NNODES) ? g_dinv[r1] : 0.f;
#pragma unroll
        for (int nt = 0; nt < 4; nt++) {
            int c2 = (wn + nt * 8) / 2 + tg;
            if (r0 < NNODES)
                outp[(size_t)r0 * 32 + c2] =
                    make_float2(acc[mt][nt][0] * dv0, acc[mt][nt][1] * dv0);
            if (r1 < NNODES)
                outp[(size_t)r1 * 32 + c2] =
                    make_float2(acc[mt][nt][2] * dv1, acc[mt][nt][3] * dv1);
        }
    }
}

// ---------------------------------------------------------------------------
// K4: CSR aggregation
// ---------------------------------------------------------------------------
__global__ __launch_bounds__(256) void k_aggr() {
    int gid = blockIdx.x * 256 + threadIdx.x;
    int v = gid >> 4;
    int q = gid & 15;
    if (v >= NNODES) return;

    float4 acc = g_bufA[(size_t)v * HID4 + q];
    int beg = g_rowptr[v];
    int end = g_rowptr[v + 1];

    int i = beg;
    for (; i + 2 <= end; i += 2) {
        int s0 = g_csrc[i];
        int s1 = g_csrc[i + 1];
        float4 t0 = __ldg(g_bufA + (size_t)s0 * HID4 + q);
        float4 t1 = __ldg(g_bufA + (size_t)s1 * HID4 + q);
        acc.x += t0.x + t1.x;
        acc.y += t0.y + t1.y;
        acc.z += t0.z + t1.z;
        acc.w += t0.w + t1.w;
    }
    if (i < end) {
        int s0 = g_csrc[i];
        float4 t0 = __ldg(g_bufA + (size_t)s0 * HID4 + q);
        acc.x += t0.x; acc.y += t0.y; acc.z += t0.z; acc.w += t0.w;
    }
    g_bufB[(size_t)v * HID4 + q] = acc;
}

// ---------------------------------------------------------------------------
// K5: layer-1 finish + GEMM2 fused (3xTF32 + cp.async pipeline)
// ---------------------------------------------------------------------------
__global__ __launch_bounds__(256) void k_layer2(const float* __restrict__ W2,
                                                const float* __restrict__ b1) {
    __shared__ float    sAraw[2][128][16];
    __shared__ uint32_t sAhi[128][20], sAlo[128][20];
    __shared__ uint32_t sBhi[16][72],  sBlo[16][72];

    const int m0   = blockIdx.x * 128;
    const int tid  = threadIdx.x;
    const int wid  = tid >> 5;
    const int lane = tid & 31;
    const int g    = lane >> 2;
    const int tg   = lane & 3;
    const int wm   = (wid >> 1) * 32;
    const int wn   = (wid & 1) * 32;

    const float* bsrc = (const float*)g_bufB;

    float acc[2][4][4];
#pragma unroll
    for (int mt = 0; mt < 2; mt++)
#pragma unroll
        for (int nt = 0; nt < 4; nt++)
#pragma unroll
            for (int c = 0; c < 4; c++) acc[mt][nt][c] = 0.f;

    {
#pragma unroll
        for (int l = 0; l < 2; l++) {
            int idx = tid + l * 256;
            int r = idx >> 2, c4 = idx & 3;
            int row = m0 + r;
            int rr = row < NNODES ? row : NNODES - 1;
            cp_async16(&sAraw[0][r][c4 * 4],
                       bsrc + (size_t)rr * HID + c4 * 4,
                       row < NNODES ? 16 : 0);
        }
        cp_commit();
    }

#pragma unroll 1
    for (int kc = 0; kc < 4; kc++) {
        if (kc < 3) {
#pragma unroll
            for (int l = 0; l < 2; l++) {
                int idx = tid + l * 256;
                int r = idx >> 2, c4 = idx & 3;
                int row = m0 + r;
                int rr = row < NNODES ? row : NNODES - 1;
                cp_async16(&sAraw[(kc + 1) & 1][r][c4 * 4],
                           bsrc + (size_t)rr * HID + (kc + 1) * 16 + c4 * 4,
                           row < NNODES ? 16 : 0);
            }
            cp_commit();
            cp_wait<1>();
        } else {
            cp_wait<0>();
        }
        __syncthreads();

        // convert phase: raw -> relu(raw*dinv+b1) -> hi/lo split
#pragma unroll
        for (int l = 0; l < 2; l++) {
            int idx = tid + l * 256;
            int r = idx >> 2, c4 = idx & 3;
            int row = m0 + r;
            float4 v = make_float4(0.f, 0.f, 0.f, 0.f);
            if (row < NNODES) {
                v = *(const float4*)&sAraw[kc & 1][r][c4 * 4];
                float dv = g_dinv[row];
                float4 bb = __ldg((const float4*)b1 + kc * 4 + c4);
                v.x = fmaxf(fmaf(v.x, dv, bb.x), 0.f);
                v.y = fmaxf(fmaf(v.y, dv, bb.y), 0.f);
                v.z = fmaxf(fmaf(v.z, dv, bb.z), 0.f);
                v.w = fmaxf(fmaf(v.w, dv, bb.w), 0.f);
            }
            uint4 h, lo;
            split_tf32(v.x, h.x, lo.x);
            split_tf32(v.y, h.y, lo.y);
            split_tf32(v.z, h.z, lo.z);
            split_tf32(v.w, h.w, lo.w);
            *(uint4*)&sAhi[r][c4 * 4] = h;
            *(uint4*)&sAlo[r][c4 * 4] = lo;
        }
        {
            int k = tid >> 4, c4 = tid & 15;
            float4 v = __ldg((const float4*)(W2 + (size_t)(kc * 16 + k) * HID) + c4);
            uint4 h, lo;
            split_tf32(v.x, h.x, lo.x);
            split_tf32(v.y, h.y, lo.y);
            split_tf32(v.z, h.z, lo.z);
            split_tf32(v.w, h.w, lo.w);
            *(uint4*)&sBhi[k][c4 * 4] = h;
            *(uint4*)&sBlo[k][c4 * 4] = lo;
        }
        __syncthreads();

#pragma unroll
        for (int s = 0; s < 2; s++) {
            int k0 = s * 8;
            uint32_t ahi[2][4], alo[2][4], bhi[4][2], blo[4][2];
#pragma unroll
            for (int mt = 0; mt < 2; mt++) {
                int r = wm + mt * 16 + g;
                ahi[mt][0] = sAhi[r    ][k0 + tg];
                ahi[mt][1] = sAhi[r + 8][k0 + tg];
                ahi[mt][2] = sAhi[r    ][k0 + tg + 4];
                ahi[mt][3] = sAhi[r + 8][k0 + tg + 4];
                alo[mt][0] = sAlo[r    ][k0 + tg];
                alo[mt][1] = sAlo[r + 8][k0 + tg];
                alo[mt][2] = sAlo[r    ][k0 + tg + 4];
                alo[mt][3] = sAlo[r + 8][k0 + tg + 4];
            }
#pragma unroll
            for (int nt = 0; nt < 4; nt++) {
                int n = wn + nt * 8 + g;
                bhi[nt][0] = sBhi[k0 + tg    ][n];
                bhi[nt][1] = sBhi[k0 + tg + 4][n];
                blo[nt][0] = sBlo[k0 + tg    ][n];
                blo[nt][1] = sBlo[k0 + tg + 4][n];
            }
#pragma unroll
            for (int mt = 0; mt < 2; mt++)
#pragma unroll
                for (int nt = 0; nt < 4; nt++) {
                    mma_tf32(acc[mt][nt], ahi[mt], bhi[nt]);
                    mma_tf32(acc[mt][nt], ahi[mt], blo[nt]);
                    mma_tf32(acc[mt][nt], alo[mt], bhi[nt]);
                }
        }
        __syncthreads();
    }

    float2* outp = (float2*)g_bufA;
#pragma unroll
    for (int mt = 0; mt < 2; mt++) {
        int r0 = m0 + wm + mt * 16 + g;
        int r1 = r0 + 8;
        float dv0 = (r0 < NNODES) ? g_dinv[r0] : 0.f;
        float dv1 = (r1 < NNODES) ? g_dinv[r1] : 0.f;
#pragma unroll
        for (int nt = 0; nt < 4; nt++) {
            int c2 = (wn + nt * 8) / 2 + tg;
            if (r0 < NNODES)
                outp[(size_t)r0 * 32 + c2] =
                    make_float2(acc[mt][nt][0] * dv0, acc[mt][nt][1] * dv0);
            if (r1 < NNODES)
                outp[(size_t)r1 * 32 + c2] =
                    make_float2(acc[mt][nt][2] * dv1, acc[mt][nt][3] * dv1);
        }
    }
}

// ---------------------------------------------------------------------------
// K6: head
// ---------------------------------------------------------------------------
__global__ __launch_bounds__(256) void k_final(const float* __restrict__ Wd,
                                               const float* __restrict__ b2,
                                               const float* __restrict__ bd,
                                               float* __restrict__ out) {
    int warp = (blockIdx.x * 256 + threadIdx.x) >> 5;
    int lane = threadIdx.x & 31;
    if (warp >= NNODES) return;
    float  dv = g_dinv[warp];
    float2 v  = *((const float2*)(g_bufB + (size_t)warp * HID4) + lane);
    float2 b  = __ldg((const float2*)b2 + lane);
    float2 w  = __ldg((const float2*)Wd + lane);
    float s = fmaxf(fmaf(v.x, dv, b.x), 0.f) * w.x
            + fmaxf(fmaf(v.y, dv, b.y), 0.f) * w.y;
#pragma unroll
    for (int o = 16; o > 0; o >>= 1)
        s += __shfl_down_sync(0xffffffffu, s, o);
    if (lane == 0) out[warp] = s + __ldg(bd);
}

// ---------------------------------------------------------------------------
extern "C" void kernel_launch(void* const* d_in, const int* in_sizes, int n_in,
                              void* d_out, int out_size) {
    const float* x   = (const float*)d_in[0];
    const int*   ei  = (const int*)d_in[1];
    const float* W1  = (const float*)d_in[2];
    const float* b1  = (const float*)d_in[3];
    const float* W2  = (const float*)d_in[4];
    const float* b2  = (const float*)d_in[5];
    const float* Wd  = (const float*)d_in[6];
    const float* bd  = (const float*)d_in[7];
    float*       out = (float*)d_out;

    k_zero  <<<(NNODES + 255) / 256, 256>>>();
    k_count <<<(NEDGES + 255) / 256, 256>>>(ei);
    k_scan1 <<<NSCANB, SCAN_T>>>();
    k_scan23<<<NSCANB, SCAN_T>>>();
    k_fill  <<<(NEDGES + 255) / 256, 256>>>(ei);

    k_gemm1<<<(NNODES + 127) / 128, 256>>>(x, W1);
    k_aggr <<<(NNODES * 16 + 255) / 256, 256>>>();

    k_layer2<<<(NNODES + 127) / 128, 256>>>(W2, b1);
    k_aggr  <<<(NNODES * 16 + 255) / 256, 256>>>();

    k_final<<<(NNODES * 32 + 255) / 256, 256>>>(Wd, b2, bd, out);
}

// round 16
// speedup vs baseline: 1.1377x; 1.1377x over previous
#include <cuda_runtime.h>
#include <cuda_fp16.h>
#include <cstdint>

#define NNODES 100000
#define NEDGES 1600000
#define F_IN   128
#define HID    64
#define HID4   (HID / 4)

#define SCAN_T 1024
#define NSCANB ((NNODES + SCAN_T - 1) / SCAN_T)   // 98

__device__ float  g_dinv[NNODES];
__device__ uint2  g_bufAh[(size_t)NNODES * 16];   // fp16 rows: 64 halfs = 16 uint2
__device__ float4 g_bufB[(size_t)NNODES * HID4];  // fp32 aggregated sums (layer1)
__device__ int    g_degi  [NNODES];
__device__ int    g_cursor[NNODES];
__device__ int    g_rowptr[NNODES + 1];
__device__ int    g_bsum  [NSCANB];
__device__ int    g_csrc  [NEDGES];

// ---------------------------------------------------------------------------
// tf32 helpers (3xTF32 split)
// ---------------------------------------------------------------------------
__device__ __forceinline__ uint32_t f2tf32(float x) {
    uint32_t r;
    asm("cvt.rna.tf32.f32 %0, %1;" : "=r"(r) : "f"(x));
    return r;
}
__device__ __forceinline__ void mma_tf32(float* d, const uint32_t* a,
                                         const uint32_t* b) {
    asm("mma.sync.aligned.m16n8k8.row.col.f32.tf32.tf32.f32 "
        "{%0,%1,%2,%3}, {%4,%5,%6,%7}, {%8,%9}, {%0,%1,%2,%3};"
        : "+f"(d[0]), "+f"(d[1]), "+f"(d[2]), "+f"(d[3])
        : "r"(a[0]), "r"(a[1]), "r"(a[2]), "r"(a[3]), "r"(b[0]), "r"(b[1]));
}
__device__ __forceinline__ void split_tf32(float x, uint32_t& hi, uint32_t& lo) {
    hi = f2tf32(x);
    lo = f2tf32(x - __uint_as_float(hi));
}
// fp16 row helpers
__device__ __forceinline__ float4 h4_to_f4(uint2 u) {
    __half2 a = *(__half2*)&u.x;
    __half2 b = *(__half2*)&u.y;
    float2 fa = __half22float2(a);
    float2 fb = __half22float2(b);
    return make_float4(fa.x, fa.y, fb.x, fb.y);
}

// ---------------------------------------------------------------------------
// CSR construction
// ---------------------------------------------------------------------------
__global__ void k_zero() {
    int v = blockIdx.x * blockDim.x + threadIdx.x;
    if (v < NNODES) { g_degi[v] = 0; g_cursor[v] = 0; }
}

__global__ void k_count(const int* __restrict__ ei) {
    int e = blockIdx.x * blockDim.x + threadIdx.x;
    if (e < NEDGES) atomicAdd(&g_degi[ei[NEDGES + e]], 1);
}

__global__ __launch_bounds__(SCAN_T) void k_scan1() {
    __shared__ int s[SCAN_T];
    int i = blockIdx.x * SCAN_T + threadIdx.x;
    int v = (i < NNODES) ? g_degi[i] : 0;
    s[threadIdx.x] = v;
    __syncthreads();
    for (int off = 1; off < SCAN_T; off <<= 1) {
        int t = (threadIdx.x >= off) ? s[threadIdx.x - off] : 0;
        __syncthreads();
        s[threadIdx.x] += t;
        __syncthreads();
    }
    if (i < NNODES) g_rowptr[i] = s[threadIdx.x] - v;
    if (threadIdx.x == SCAN_T - 1) g_bsum[blockIdx.x] = s[SCAN_T - 1];
}

__global__ __launch_bounds__(SCAN_T) void k_scan23() {
    __shared__ int sp[128];
    int t = threadIdx.x;
    if (t < 128) sp[t] = (t < blockIdx.x && t < NSCANB) ? g_bsum[t] : 0;
    __syncthreads();
    for (int off = 64; off > 0; off >>= 1) {
        if (t < off) sp[t] += sp[t + off];
        __syncthreads();
    }
    int prefix = sp[0];
    int i = blockIdx.x * SCAN_T + t;
    if (i < NNODES) {
        g_rowptr[i] += prefix;
        g_dinv[i] = rsqrtf((float)(g_degi[i] + 1));
    }
    if (blockIdx.x == 0 && t == 0) g_rowptr[NNODES] = NEDGES;
}

__global__ void k_fill(const int* __restrict__ ei) {
    int e = blockIdx.x * blockDim.x + threadIdx.x;
    if (e < NEDGES) {
        int s = ei[e];
        int d = ei[NEDGES + e];
        int pos = g_rowptr[d] + atomicAdd(&g_cursor[d], 1);
        g_csrc[pos] = s;
    }
}

// ---------------------------------------------------------------------------
// K3: GEMM1  bufAh = fp16((x @ W1) * dinv[row])   -- 3xTF32 mma.sync (R13 body)
// ---------------------------------------------------------------------------
__global__ __launch_bounds__(256) void k_gemm1(const float* __restrict__ x,
                                               const float* __restrict__ W1) {
    __shared__ uint32_t sAhi[128][20], sAlo[128][20];
    __shared__ uint32_t sBhi[16][72],  sBlo[16][72];

    const int m0   = blockIdx.x * 128;
    const int tid  = threadIdx.x;
    const int wid  = tid >> 5;
    const int lane = tid & 31;
    const int g    = lane >> 2;
    const int tg   = lane & 3;
    const int wm   = (wid >> 1) * 32;
    const int wn   = (wid & 1) * 32;

    float acc[2][4][4];
#pragma unroll
    for (int mt = 0; mt < 2; mt++)
#pragma unroll
        for (int nt = 0; nt < 4; nt++)
#pragma unroll
            for (int c = 0; c < 4; c++) acc[mt][nt][c] = 0.f;

#pragma unroll 1
    for (int kc = 0; kc < 8; kc++) {
#pragma unroll
        for (int l = 0; l < 2; l++) {
            int idx = tid + l * 256;
            int r = idx >> 2, c4 = idx & 3;
            int row = m0 + r;
            float4 v = make_float4(0.f, 0.f, 0.f, 0.f);
            if (row < NNODES)
                v = __ldg((const float4*)(x + (size_t)row * F_IN + kc * 16) + c4);
            uint4 h, lo;
            split_tf32(v.x, h.x, lo.x);
            split_tf32(v.y, h.y, lo.y);
            split_tf32(v.z, h.z, lo.z);
            split_tf32(v.w, h.w, lo.w);
            *(uint4*)&sAhi[r][c4 * 4] = h;
            *(uint4*)&sAlo[r][c4 * 4] = lo;
        }
        {
            int k = tid >> 4, c4 = tid & 15;
            float4 v = __ldg((const float4*)(W1 + (size_t)(kc * 16 + k) * HID) + c4);
            uint4 h, lo;
            split_tf32(v.x, h.x, lo.x);
            split_tf32(v.y, h.y, lo.y);
            split_tf32(v.z, h.z, lo.z);
            split_tf32(v.w, h.w, lo.w);
            *(uint4*)&sBhi[k][c4 * 4] = h;
            *(uint4*)&sBlo[k][c4 * 4] = lo;
        }
        __syncthreads();

#pragma unroll
        for (int s = 0; s < 2; s++) {
            int k0 = s * 8;
            uint32_t ahi[2][4], alo[2][4], bhi[4][2], blo[4][2];
#pragma unroll
            for (int mt = 0; mt < 2; mt++) {
                int r = wm + mt * 16 + g;
                ahi[mt][0] = sAhi[r    ][k0 + tg];
                ahi[mt][1] = sAhi[r + 8][k0 + tg];
                ahi[mt][2] = sAhi[r    ][k0 + tg + 4];
                ahi[mt][3] = sAhi[r + 8][k0 + tg + 4];
                alo[mt][0] = sAlo[r    ][k0 + tg];
                alo[mt][1] = sAlo[r + 8][k0 + tg];
                alo[mt][2] = sAlo[r    ][k0 + tg + 4];
                alo[mt][3] = sAlo[r + 8][k0 + tg + 4];
            }
#pragma unroll
            for (int nt = 0; nt < 4; nt++) {
                int n = wn + nt * 8 + g;
                bhi[nt][0] = sBhi[k0 + tg    ][n];
                bhi[nt][1] = sBhi[k0 + tg + 4][n];
                blo[nt][0] = sBlo[k0 + tg    ][n];
                blo[nt][1] = sBlo[k0 + tg + 4][n];
            }
#pragma unroll
            for (int mt = 0; mt < 2; mt++)
#pragma unroll
                for (int nt = 0; nt < 4; nt++) {
                    mma_tf32(acc[mt][nt], ahi[mt], bhi[nt]);
                    mma_tf32(acc[mt][nt], ahi[mt], blo[nt]);
                    mma_tf32(acc[mt][nt], alo[mt], bhi[nt]);
                }
        }
        __syncthreads();
    }

    // epilogue: scale by dinv, store fp16 pairs
    __half2* outp = (__half2*)g_bufAh;
#pragma unroll
    for (int mt = 0; mt < 2; mt++) {
        int r0 = m0 + wm + mt * 16 + g;
        int r1 = r0 + 8;
        float dv0 = (r0 < NNODES) ? g_dinv[r0] : 0.f;
        float dv1 = (r1 < NNODES) ? g_dinv[r1] : 0.f;
#pragma unroll
        for (int nt = 0; nt < 4; nt++) {
            int c2 = (wn + nt * 8) / 2 + tg;
            if (r0 < NNODES)
                outp[(size_t)r0 * 32 + c2] =
                    __floats2half2_rn(acc[mt][nt][0] * dv0, acc[mt][nt][1] * dv0);
            if (r1 < NNODES)
                outp[(size_t)r1 * 32 + c2] =
                    __floats2half2_rn(acc[mt][nt][2] * dv1, acc[mt][nt][3] * dv1);
        }
    }
}

// ---------------------------------------------------------------------------
// K4: aggr1: bufB[v] = f32( bufAh[v] + sum_{s in N_in(v)} bufAh[s] )
//   16 threads/node, 8B fp16 gathers (half traffic), fp32 accumulation.
// ---------------------------------------------------------------------------
__global__ __launch_bounds__(256) void k_aggr1() {
    int gid = blockIdx.x * 256 + threadIdx.x;
    int v = gid >> 4;
    int q = gid & 15;
    if (v >= NNODES) return;

    float4 acc = h4_to_f4(g_bufAh[(size_t)v * 16 + q]);   // self-loop
    int beg = g_rowptr[v];
    int end = g_rowptr[v + 1];

    int i = beg;
    for (; i + 2 <= end; i += 2) {
        int s0 = g_csrc[i];
        int s1 = g_csrc[i + 1];
        float4 t0 = h4_to_f4(__ldg(g_bufAh + (size_t)s0 * 16 + q));
        float4 t1 = h4_to_f4(__ldg(g_bufAh + (size_t)s1 * 16 + q));
        acc.x += t0.x + t1.x;
        acc.y += t0.y + t1.y;
        acc.z += t0.z + t1.z;
        acc.w += t0.w + t1.w;
    }
    if (i < end) {
        int s0 = g_csrc[i];
        float4 t0 = h4_to_f4(__ldg(g_bufAh + (size_t)s0 * 16 + q));
        acc.x += t0.x; acc.y += t0.y; acc.z += t0.z; acc.w += t0.w;
    }
    g_bufB[(size_t)v * HID4 + q] = acc;
}

// ---------------------------------------------------------------------------
// K5: layer-1 finish + GEMM2 fused (3xTF32, R13 body):
//   h1 = relu(bufB*dinv + b1);  bufAh = fp16((h1 @ W2) * dinv)
// ---------------------------------------------------------------------------
__global__ __launch_bounds__(256) void k_layer2(const float* __restrict__ W2,
                                                const float* __restrict__ b1) {
    __shared__ uint32_t sAhi[128][20], sAlo[128][20];
    __shared__ uint32_t sBhi[16][72],  sBlo[16][72];

    const int m0   = blockIdx.x * 128;
    const int tid  = threadIdx.x;
    const int wid  = tid >> 5;
    const int lane = tid & 31;
    const int g    = lane >> 2;
    const int tg   = lane & 3;
    const int wm   = (wid >> 1) * 32;
    const int wn   = (wid & 1) * 32;

    float acc[2][4][4];
#pragma unroll
    for (int mt = 0; mt < 2; mt++)
#pragma unroll
        for (int nt = 0; nt < 4; nt++)
#pragma unroll
            for (int c = 0; c < 4; c++) acc[mt][nt][c] = 0.f;

#pragma unroll 1
    for (int kc = 0; kc < 4; kc++) {
#pragma unroll
        for (int l = 0; l < 2; l++) {
            int idx = tid + l * 256;
            int r = idx >> 2, c4 = idx & 3;
            int row = m0 + r;
            float4 v = make_float4(0.f, 0.f, 0.f, 0.f);
            if (row < NNODES) {
                v = g_bufB[(size_t)row * HID4 + kc * 4 + c4];
                float dv = g_dinv[row];
                float4 bb = __ldg((const float4*)b1 + kc * 4 + c4);
                v.x = fmaxf(fmaf(v.x, dv, bb.x), 0.f);
                v.y = fmaxf(fmaf(v.y, dv, bb.y), 0.f);
                v.z = fmaxf(fmaf(v.z, dv, bb.z), 0.f);
                v.w = fmaxf(fmaf(v.w, dv, bb.w), 0.f);
            }
            uint4 h, lo;
            split_tf32(v.x, h.x, lo.x);
            split_tf32(v.y, h.y, lo.y);
            split_tf32(v.z, h.z, lo.z);
            split_tf32(v.w, h.w, lo.w);
            *(uint4*)&sAhi[r][c4 * 4] = h;
            *(uint4*)&sAlo[r][c4 * 4] = lo;
        }
        {
            int k = tid >> 4, c4 = tid & 15;
            float4 v = __ldg((const float4*)(W2 + (size_t)(kc * 16 + k) * HID) + c4);
            uint4 h, lo;
            split_tf32(v.x, h.x, lo.x);
            split_tf32(v.y, h.y, lo.y);
            split_tf32(v.z, h.z, lo.z);
            split_tf32(v.w, h.w, lo.w);
            *(uint4*)&sBhi[k][c4 * 4] = h;
            *(uint4*)&sBlo[k][c4 * 4] = lo;
        }
        __syncthreads();

#pragma unroll
        for (int s = 0; s < 2; s++) {
            int k0 = s * 8;
            uint32_t ahi[2][4], alo[2][4], bhi[4][2], blo[4][2];
#pragma unroll
            for (int mt = 0; mt < 2; mt++) {
                int r = wm + mt * 16 + g;
                ahi[mt][0] = sAhi[r    ][k0 + tg];
                ahi[mt][1] = sAhi[r + 8][k0 + tg];
                ahi[mt][2] = sAhi[r    ][k0 + tg + 4];
                ahi[mt][3] = sAhi[r + 8][k0 + tg + 4];
                alo[mt][0] = sAlo[r    ][k0 + tg];
                alo[mt][1] = sAlo[r + 8][k0 + tg];
                alo[mt][2] = sAlo[r    ][k0 + tg + 4];
                alo[mt][3] = sAlo[r + 8][k0 + tg + 4];
            }
#pragma unroll
            for (int nt = 0; nt < 4; nt++) {
                int n = wn + nt * 8 + g;
                bhi[nt][0] = sBhi[k0 + tg    ][n];
                bhi[nt][1] = sBhi[k0 + tg + 4][n];
                blo[nt][0] = sBlo[k0 + tg    ][n];
                blo[nt][1] = sBlo[k0 + tg + 4][n];
            }
#pragma unroll
            for (int mt = 0; mt < 2; mt++)
#pragma unroll
                for (int nt = 0; nt < 4; nt++) {
                    mma_tf32(acc[mt][nt], ahi[mt], bhi[nt]);
                    mma_tf32(acc[mt][nt], ahi[mt], blo[nt]);
                    mma_tf32(acc[mt][nt], alo[mt], bhi[nt]);
                }
        }
        __syncthreads();
    }

    __half2* outp = (__half2*)g_bufAh;
#pragma unroll
    for (int mt = 0; mt < 2; mt++) {
        int r0 = m0 + wm + mt * 16 + g;
        int r1 = r0 + 8;
        float dv0 = (r0 < NNODES) ? g_dinv[r0] : 0.f;
        float dv1 = (r1 < NNODES) ? g_dinv[r1] : 0.f;
#pragma unroll
        for (int nt = 0; nt < 4; nt++) {
            int c2 = (wn + nt * 8) / 2 + tg;
            if (r0 < NNODES)
                outp[(size_t)r0 * 32 + c2] =
                    __floats2half2_rn(acc[mt][nt][0] * dv0, acc[mt][nt][1] * dv0);
            if (r1 < NNODES)
                outp[(size_t)r1 * 32 + c2] =
                    __floats2half2_rn(acc[mt][nt][2] * dv1, acc[mt][nt][3] * dv1);
        }
    }
}

// ---------------------------------------------------------------------------
// K6: fused aggr2 + head:
//   acc = bufAh[v] + sum bufAh[srcs]  (fp32 accum)
//   out[v] = sum_q relu(acc*dinv + b2).Wd  (16-lane shuffle reduce) + bd
// ---------------------------------------------------------------------------
__global__ __launch_bounds__(256) void k_aggrf(const float* __restrict__ b2,
                                               const float* __restrict__ Wd,
                                               const float* __restrict__ bd,
                                               float* __restrict__ out) {
    int gid = blockIdx.x * 256 + threadIdx.x;
    int v = gid >> 4;
    int q = gid & 15;
    if (v >= NNODES) return;

    float4 acc = h4_to_f4(g_bufAh[(size_t)v * 16 + q]);   // self-loop
    int beg = g_rowptr[v];
    int end = g_rowptr[v + 1];

    int i = beg;
    for (; i + 2 <= end; i += 2) {
        int s0 = g_csrc[i];
        int s1 = g_csrc[i + 1];
        float4 t0 = h4_to_f4(__ldg(g_bufAh + (size_t)s0 * 16 + q));
        float4 t1 = h4_to_f4(__ldg(g_bufAh + (size_t)s1 * 16 + q));
        acc.x += t0.x + t1.x;
        acc.y += t0.y + t1.y;
        acc.z += t0.z + t1.z;
        acc.w += t0.w + t1.w;
    }
    if (i < end) {
        int s0 = g_csrc[i];
        float4 t0 = h4_to_f4(__ldg(g_bufAh + (size_t)s0 * 16 + q));
        acc.x += t0.x; acc.y += t0.y; acc.z += t0.z; acc.w += t0.w;
    }

    float  dv = g_dinv[v];
    float4 bb = __ldg((const float4*)b2 + q);
    float4 ww = __ldg((const float4*)Wd + q);
    float s = fmaxf(fmaf(acc.x, dv, bb.x), 0.f) * ww.x
            + fmaxf(fmaf(acc.y, dv, bb.y), 0.f) * ww.y
            + fmaxf(fmaf(acc.z, dv, bb.z), 0.f) * ww.z
            + fmaxf(fmaf(acc.w, dv, bb.w), 0.f) * ww.w;
#pragma unroll
    for (int o = 8; o > 0; o >>= 1)
        s += __shfl_down_sync(0xffffffffu, s, o);   // reduce within 16-lane group
    if (q == 0) out[v] = s + __ldg(bd);
}

// ---------------------------------------------------------------------------
extern "C" void kernel_launch(void* const* d_in, const int* in_sizes, int n_in,
                              void* d_out, int out_size) {
    const float* x   = (const float*)d_in[0];
    const int*   ei  = (const int*)d_in[1];
    const float* W1  = (const float*)d_in[2];
    const float* b1  = (const float*)d_in[3];
    const float* W2  = (const float*)d_in[4];
    const float* b2  = (const float*)d_in[5];
    const float* Wd  = (const float*)d_in[6];
    const float* bd  = (const float*)d_in[7];
    float*       out = (float*)d_out;

    k_zero  <<<(NNODES + 255) / 256, 256>>>();
    k_count <<<(NEDGES + 255) / 256, 256>>>(ei);
    k_scan1 <<<NSCANB, SCAN_T>>>();
    k_scan23<<<NSCANB, SCAN_T>>>();
    k_fill  <<<(NEDGES + 255) / 256, 256>>>(ei);

    k_gemm1<<<(NNODES + 127) / 128, 256>>>(x, W1);
    k_aggr1<<<(NNODES * 16 + 255) / 256, 256>>>();

    k_layer2<<<(NNODES + 127) / 128, 256>>>(W2, b1);
    k_aggrf <<<(NNODES * 16 + 255) / 256, 256>>>(b2, Wd, bd, out);
}

// round 17
// speedup vs baseline: 1.1944x; 1.0498x over previous
#include <cuda_runtime.h>
#include <cuda_fp16.h>
#include <cstdint>

#define NNODES 100000
#define NEDGES 1600000
#define F_IN   128
#define HID    64

#define NSCANB 98   // ceil(100000 / 1024)

__device__ float  g_dinv[NNODES];
__device__ uint2  g_bufAh[(size_t)NNODES * 16];   // fp16 rows (gather source)
__device__ uint2  g_bufBh[(size_t)NNODES * 16];   // fp16 rows (layer1 aggregate)
__device__ int    g_degi  [NNODES];
__device__ int    g_cursor[NNODES];
__device__ int    g_rowptr[NNODES + 1];
__device__ int    g_bsum  [NSCANB];
__device__ int    g_csrc  [NEDGES];

// ---------------------------------------------------------------------------
// helpers
// ---------------------------------------------------------------------------
__device__ __forceinline__ uint32_t f2tf32(float x) {
    uint32_t r;
    asm("cvt.rna.tf32.f32 %0, %1;" : "=r"(r) : "f"(x));
    return r;
}
__device__ __forceinline__ void mma_tf32(float* d, const uint32_t* a,
                                         const uint32_t* b) {
    asm("mma.sync.aligned.m16n8k8.row.col.f32.tf32.tf32.f32 "
        "{%0,%1,%2,%3}, {%4,%5,%6,%7}, {%8,%9}, {%0,%1,%2,%3};"
        : "+f"(d[0]), "+f"(d[1]), "+f"(d[2]), "+f"(d[3])
        : "r"(a[0]), "r"(a[1]), "r"(a[2]), "r"(a[3]), "r"(b[0]), "r"(b[1]));
}
__device__ __forceinline__ void split_tf32(float x, uint32_t& hi, uint32_t& lo) {
    hi = f2tf32(x);
    lo = f2tf32(x - __uint_as_float(hi));
}
__device__ __forceinline__ float4 h4_to_f4(uint2 u) {
    __half2 a = *(__half2*)&u.x;
    __half2 b = *(__half2*)&u.y;
    float2 fa = __half22float2(a);
    float2 fb = __half22float2(b);
    return make_float4(fa.x, fa.y, fb.x, fb.y);
}
__device__ __forceinline__ uint2 f4_to_h4(float4 v) {
    __half2 h0 = __floats2half2_rn(v.x, v.y);
    __half2 h1 = __floats2half2_rn(v.z, v.w);
    uint2 u;
    u.x = *(uint32_t*)&h0;
    u.y = *(uint32_t*)&h1;
    return u;
}

// ---------------------------------------------------------------------------
// CSR construction
// ---------------------------------------------------------------------------
__global__ void k_zero() {
    int v = blockIdx.x * blockDim.x + threadIdx.x;
    if (v < NNODES) { g_degi[v] = 0; g_cursor[v] = 0; }
}

__global__ void k_count(const int* __restrict__ ei) {
    int e = blockIdx.x * blockDim.x + threadIdx.x;
    if (e < NEDGES) atomicAdd(&g_degi[ei[NEDGES + e]], 1);
}

// shuffle-based scan: 256 threads, 4 elems/thread, 2 syncs
__global__ __launch_bounds__(256) void k_scan1() {
    int t = threadIdx.x;
    int base = blockIdx.x * 1024 + t * 4;
    int4 d;
    if (base + 3 < NNODES) d = *(const int4*)(g_degi + base);
    else {
        d.x = (base     < NNODES) ? g_degi[base]     : 0;
        d.y = (base + 1 < NNODES) ? g_degi[base + 1] : 0;
        d.z = (base + 2 < NNODES) ? g_degi[base + 2] : 0;
        d.w = (base + 3 < NNODES) ? g_degi[base + 3] : 0;
    }
    int tsum = d.x + d.y + d.z + d.w;
    int lane = t & 31, w = t >> 5;
    int inc = tsum;
#pragma unroll
    for (int off = 1; off < 32; off <<= 1) {
        int n = __shfl_up_sync(0xffffffffu, inc, off);
        if (lane >= off) inc += n;
    }
    __shared__ int wsum[8];
    if (lane == 31) wsum[w] = inc;
    __syncthreads();
    if (t == 0) {
        int run = 0;
#pragma unroll
        for (int j = 0; j < 8; j++) { int tmp = wsum[j]; wsum[j] = run; run += tmp; }
    }
    __syncthreads();
    int p = wsum[w] + inc - tsum;          // block-local exclusive prefix
    if (base     < NNODES) g_rowptr[base]     = p;
    p += d.x;
    if (base + 1 < NNODES) g_rowptr[base + 1] = p;
    p += d.y;
    if (base + 2 < NNODES) g_rowptr[base + 2] = p;
    p += d.z;
    if (base + 3 < NNODES) g_rowptr[base + 3] = p;
    if (t == 255) g_bsum[blockIdx.x] = wsum[7] + inc;   // block total
}

// block-prefix apply + dinv, 256 threads, 4 elems/thread, 1 sync
__global__ __launch_bounds__(256) void k_scan23() {
    __shared__ int part[8];
    int t = threadIdx.x;
    int v = (t < blockIdx.x && t < NSCANB) ? g_bsum[t] : 0;
#pragma unroll
    for (int off = 16; off > 0; off >>= 1)
        v += __shfl_down_sync(0xffffffffu, v, off);
    if ((t & 31) == 0) part[t >> 5] = v;
    __syncthreads();
    int prefix = part[0] + part[1] + part[2] + part[3]
               + part[4] + part[5] + part[6] + part[7];
    int base = blockIdx.x * 1024 + t * 4;
#pragma unroll
    for (int j = 0; j < 4; j++) {
        int i = base + j;
        if (i < NNODES) {
            g_rowptr[i] += prefix;
            g_dinv[i] = rsqrtf((float)(g_degi[i] + 1));
        }
    }
    if (blockIdx.x == 0 && t == 0) g_rowptr[NNODES] = NEDGES;
}

// ---------------------------------------------------------------------------
// K3: GEMM1 (3xTF32) + fused CSR fill tail.
//   bufAh = fp16((x @ W1) * dinv[row]); then each block fills an edge slice.
// ---------------------------------------------------------------------------
__global__ __launch_bounds__(256) void k_gemm1(const float* __restrict__ x,
                                               const float* __restrict__ W1,
                                               const int* __restrict__ ei) {
    __shared__ uint32_t sAhi[128][20], sAlo[128][20];
    __shared__ uint32_t sBhi[16][72],  sBlo[16][72];

    const int m0   = blockIdx.x * 128;
    const int tid  = threadIdx.x;
    const int wid  = tid >> 5;
    const int lane = tid & 31;
    const int g    = lane >> 2;
    const int tg   = lane & 3;
    const int wm   = (wid >> 1) * 32;
    const int wn   = (wid & 1) * 32;

    float acc[2][4][4];
#pragma unroll
    for (int mt = 0; mt < 2; mt++)
#pragma unroll
        for (int nt = 0; nt < 4; nt++)
#pragma unroll
            for (int c = 0; c < 4; c++) acc[mt][nt][c] = 0.f;

#pragma unroll 1
    for (int kc = 0; kc < 8; kc++) {
#pragma unroll
        for (int l = 0; l < 2; l++) {
            int idx = tid + l * 256;
            int r = idx >> 2, c4 = idx & 3;
            int row = m0 + r;
            float4 v = make_float4(0.f, 0.f, 0.f, 0.f);
            if (row < NNODES)
                v = __ldg((const float4*)(x + (size_t)row * F_IN + kc * 16) + c4);
            uint4 h, lo;
            split_tf32(v.x, h.x, lo.x);
            split_tf32(v.y, h.y, lo.y);
            split_tf32(v.z, h.z, lo.z);
            split_tf32(v.w, h.w, lo.w);
            *(uint4*)&sAhi[r][c4 * 4] = h;
            *(uint4*)&sAlo[r][c4 * 4] = lo;
        }
        {
            int k = tid >> 4, c4 = tid & 15;
            float4 v = __ldg((const float4*)(W1 + (size_t)(kc * 16 + k) * HID) + c4);
            uint4 h, lo;
            split_tf32(v.x, h.x, lo.x);
            split_tf32(v.y, h.y, lo.y);
            split_tf32(v.z, h.z, lo.z);
            split_tf32(v.w, h.w, lo.w);
            *(uint4*)&sBhi[k][c4 * 4] = h;
            *(uint4*)&sBlo[k][c4 * 4] = lo;
        }
        __syncthreads();

#pragma unroll
        for (int s = 0; s < 2; s++) {
            int k0 = s * 8;
            uint32_t ahi[2][4], alo[2][4], bhi[4][2], blo[4][2];
#pragma unroll
            for (int mt = 0; mt < 2; mt++) {
                int r = wm + mt * 16 + g;
                ahi[mt][0] = sAhi[r    ][k0 + tg];
                ahi[mt][1] = sAhi[r + 8][k0 + tg];
                ahi[mt][2] = sAhi[r    ][k0 + tg + 4];
                ahi[mt][3] = sAhi[r + 8][k0 + tg + 4];
                alo[mt][0] = sAlo[r    ][k0 + tg];
                alo[mt][1] = sAlo[r + 8][k0 + tg];
                alo[mt][2] = sAlo[r    ][k0 + tg + 4];
                alo[mt][3] = sAlo[r + 8][k0 + tg + 4];
            }
#pragma unroll
            for (int nt = 0; nt < 4; nt++) {
                int n = wn + nt * 8 + g;
                bhi[nt][0] = sBhi[k0 + tg    ][n];
                bhi[nt][1] = sBhi[k0 + tg + 4][n];
                blo[nt][0] = sBlo[k0 + tg    ][n];
                blo[nt][1] = sBlo[k0 + tg + 4][n];
            }
#pragma unroll
            for (int mt = 0; mt < 2; mt++)
#pragma unroll
                for (int nt = 0; nt < 4; nt++) {
                    mma_tf32(acc[mt][nt], ahi[mt], bhi[nt]);
                    mma_tf32(acc[mt][nt], ahi[mt], blo[nt]);
                    mma_tf32(acc[mt][nt], alo[mt], bhi[nt]);
                }
        }
        __syncthreads();
    }

    // epilogue: scale by dinv, store fp16 pairs
    __half2* outp = (__half2*)g_bufAh;
#pragma unroll
    for (int mt = 0; mt < 2; mt++) {
        int r0 = m0 + wm + mt * 16 + g;
        int r1 = r0 + 8;
        float dv0 = (r0 < NNODES) ? g_dinv[r0] : 0.f;
        float dv1 = (r1 < NNODES) ? g_dinv[r1] : 0.f;
#pragma unroll
        for (int nt = 0; nt < 4; nt++) {
            int c2 = (wn + nt * 8) / 2 + tg;
            if (r0 < NNODES)
                outp[(size_t)r0 * 32 + c2] =
                    __floats2half2_rn(acc[mt][nt][0] * dv0, acc[mt][nt][1] * dv0);
            if (r1 < NNODES)
                outp[(size_t)r1 * 32 + c2] =
                    __floats2half2_rn(acc[mt][nt][2] * dv1, acc[mt][nt][3] * dv1);
        }
    }

    // fused CSR fill tail: grid-stride over edges (overlaps with other blocks'
    // GEMM phases; ordering vs k_aggr1 guaranteed by kernel boundary)
    int stride = gridDim.x * 256;
    for (int e = blockIdx.x * 256 + tid; e < NEDGES; e += stride) {
        int s = ei[e];
        int d = ei[NEDGES + e];
        int pos = g_rowptr[d] + atomicAdd(&g_cursor[d], 1);
        g_csrc[pos] = s;
    }
}

// ---------------------------------------------------------------------------
// K4: aggr1: bufBh = fp16( bufAh[v] + sum_{s in N_in(v)} bufAh[s] )
// ---------------------------------------------------------------------------
__global__ __launch_bounds__(256) void k_aggr1() {
    int gid = blockIdx.x * 256 + threadIdx.x;
    int v = gid >> 4;
    int q = gid & 15;
    if (v >= NNODES) return;

    float4 acc = h4_to_f4(g_bufAh[(size_t)v * 16 + q]);   // self-loop
    int beg = g_rowptr[v];
    int end = g_rowptr[v + 1];

    int i = beg;
    for (; i + 2 <= end; i += 2) {
        int s0 = g_csrc[i];
        int s1 = g_csrc[i + 1];
        float4 t0 = h4_to_f4(__ldg(g_bufAh + (size_t)s0 * 16 + q));
        float4 t1 = h4_to_f4(__ldg(g_bufAh + (size_t)s1 * 16 + q));
        acc.x += t0.x + t1.x;
        acc.y += t0.y + t1.y;
        acc.z += t0.z + t1.z;
        acc.w += t0.w + t1.w;
    }
    if (i < end) {
        int s0 = g_csrc[i];
        float4 t0 = h4_to_f4(__ldg(g_bufAh + (size_t)s0 * 16 + q));
        acc.x += t0.x; acc.y += t0.y; acc.z += t0.z; acc.w += t0.w;
    }
    g_bufBh[(size_t)v * 16 + q] = f4_to_h4(acc);
}

// ---------------------------------------------------------------------------
// K5: layer-1 finish + GEMM2 fused (3xTF32):
//   h1 = relu(bufBh*dinv + b1);  bufAh = fp16((h1 @ W2) * dinv)
// ---------------------------------------------------------------------------
__global__ __launch_bounds__(256) void k_layer2(const float* __restrict__ W2,
                                                const float* __restrict__ b1) {
    __shared__ uint32_t sAhi[128][20], sAlo[128][20];
    __shared__ uint32_t sBhi[16][72],  sBlo[16][72];

    const int m0   = blockIdx.x * 128;
    const int tid  = threadIdx.x;
    const int wid  = tid >> 5;
    const int lane = tid & 31;
    const int g    = lane >> 2;
    const int tg   = lane & 3;
    const int wm   = (wid >> 1) * 32;
    const int wn   = (wid & 1) * 32;

    float acc[2][4][4];
#pragma unroll
    for (int mt = 0; mt < 2; mt++)
#pragma unroll
        for (int nt = 0; nt < 4; nt++)
#pragma unroll
            for (int c = 0; c < 4; c++) acc[mt][nt][c] = 0.f;

#pragma unroll 1
    for (int kc = 0; kc < 4; kc++) {
#pragma unroll
        for (int l = 0; l < 2; l++) {
            int idx = tid + l * 256;
            int r = idx >> 2, c4 = idx & 3;
            int row = m0 + r;
            float4 v = make_float4(0.f, 0.f, 0.f, 0.f);
            if (row < NNODES) {
                v = h4_to_f4(g_bufBh[(size_t)row * 16 + kc * 4 + c4]);
                float dv = g_dinv[row];
                float4 bb = __ldg((const float4*)b1 + kc * 4 + c4);
                v.x = fmaxf(fmaf(v.x, dv, bb.x), 0.f);
                v.y = fmaxf(fmaf(v.y, dv, bb.y), 0.f);
                v.z = fmaxf(fmaf(v.z, dv, bb.z), 0.f);
                v.w = fmaxf(fmaf(v.w, dv, bb.w), 0.f);
            }
            uint4 h, lo;
            split_tf32(v.x, h.x, lo.x);
            split_tf32(v.y, h.y, lo.y);
            split_tf32(v.z, h.z, lo.z);
            split_tf32(v.w, h.w, lo.w);
            *(uint4*)&sAhi[r][c4 * 4] = h;
            *(uint4*)&sAlo[r][c4 * 4] = lo;
        }
        {
            int k = tid >> 4, c4 = tid & 15;
            float4 v = __ldg((const float4*)(W2 + (size_t)(kc * 16 + k) * HID) + c4);
            uint4 h, lo;
            split_tf32(v.x, h.x, lo.x);
            split_tf32(v.y, h.y, lo.y);
            split_tf32(v.z, h.z, lo.z);
            split_tf32(v.w, h.w, lo.w);
            *(uint4*)&sBhi[k][c4 * 4] = h;
            *(uint4*)&sBlo[k][c4 * 4] = lo;
        }
        __syncthreads();

#pragma unroll
        for (int s = 0; s < 2; s++) {
            int k0 = s * 8;
            uint32_t ahi[2][4], alo[2][4], bhi[4][2], blo[4][2];
#pragma unroll
            for (int mt = 0; mt < 2; mt++) {
                int r = wm + mt * 16 + g;
                ahi[mt][0] = sAhi[r    ][k0 + tg];
                ahi[mt][1] = sAhi[r + 8][k0 + tg];
                ahi[mt][2] = sAhi[r    ][k0 + tg + 4];
                ahi[mt][3] = sAhi[r + 8][k0 + tg + 4];
                alo[mt][0] = sAlo[r    ][k0 + tg];
                alo[mt][1] = sAlo[r + 8][k0 + tg];
                alo[mt][2] = sAlo[r    ][k0 + tg + 4];
                alo[mt][3] = sAlo[r + 8][k0 + tg + 4];
            }
#pragma unroll
            for (int nt = 0; nt < 4; nt++) {
                int n = wn + nt * 8 + g;
                bhi[nt][0] = sBhi[k0 + tg    ][n];
                bhi[nt][1] = sBhi[k0 + tg + 4][n];
                blo[nt][0] = sBlo[k0 + tg    ][n];
                blo[nt][1] = sBlo[k0 + tg + 4][n];
            }
#pragma unroll
            for (int mt = 0; mt < 2; mt++)
#pragma unroll
                for (int nt = 0; nt < 4; nt++) {
                    mma_tf32(acc[mt][nt], ahi[mt], bhi[nt]);
                    mma_tf32(acc[mt][nt], ahi[mt], blo[nt]);
                    mma_tf32(acc[mt][nt], alo[mt], bhi[nt]);
                }
        }
        __syncthreads();
    }

    __half2* outp = (__half2*)g_bufAh;
#pragma unroll
    for (int mt = 0; mt < 2; mt++) {
        int r0 = m0 + wm + mt * 16 + g;
        int r1 = r0 + 8;
        float dv0 = (r0 < NNODES) ? g_dinv[r0] : 0.f;
        float dv1 = (r1 < NNODES) ? g_dinv[r1] : 0.f;
#pragma unroll
        for (int nt = 0; nt < 4; nt++) {
            int c2 = (wn + nt * 8) / 2 + tg;
            if (r0 < NNODES)
                outp[(size_t)r0 * 32 + c2] =
                    __floats2half2_rn(acc[mt][nt][0] * dv0, acc[mt][nt][1] * dv0);
            if (r1 < NNODES)
                outp[(size_t)r1 * 32 + c2] =
                    __floats2half2_rn(acc[mt][nt][2] * dv1, acc[mt][nt][3] * dv1);
        }
    }
}

// ---------------------------------------------------------------------------
// K6: fused aggr2 + head
// ---------------------------------------------------------------------------
__global__ __launch_bounds__(256) void k_aggrf(const float* __restrict__ b2,
                                               const float* __restrict__ Wd,
                                               const float* __restrict__ bd,
                                               float* __restrict__ out) {
    int gid = blockIdx.x * 256 + threadIdx.x;
    int v = gid >> 4;
    int q = gid & 15;
    if (v >= NNODES) return;

    float4 acc = h4_to_f4(g_bufAh[(size_t)v * 16 + q]);   // self-loop
    int beg = g_rowptr[v];
    int end = g_rowptr[v + 1];

    int i = beg;
    for (; i + 2 <= end; i += 2) {
        int s0 = g_csrc[i];
        int s1 = g_csrc[i + 1];
        float4 t0 = h4_to_f4(__ldg(g_bufAh + (size_t)s0 * 16 + q));
        float4 t1 = h4_to_f4(__ldg(g_bufAh + (size_t)s1 * 16 + q));
        acc.x += t0.x + t1.x;
        acc.y += t0.y + t1.y;
        acc.z += t0.z + t1.z;
        acc.w += t0.w + t1.w;
    }
    if (i < end) {
        int s0 = g_csrc[i];
        float4 t0 = h4_to_f4(__ldg(g_bufAh + (size_t)s0 * 16 + q));
        acc.x += t0.x; acc.y += t0.y; acc.z += t0.z; acc.w += t0.w;
    }

    float  dv = g_dinv[v];
    float4 bb = __ldg((const float4*)b2 + q);
    float4 ww = __ldg((const float4*)Wd + q);
    float s = fmaxf(fmaf(acc.x, dv, bb.x), 0.f) * ww.x
            + fmaxf(fmaf(acc.y, dv, bb.y), 0.f) * ww.y
            + fmaxf(fmaf(acc.z, dv, bb.z), 0.f) * ww.z
            + fmaxf(fmaf(acc.w, dv, bb.w), 0.f) * ww.w;
#pragma unroll
    for (int o = 8; o > 0; o >>= 1)
        s += __shfl_down_sync(0xffffffffu, s, o);
    if (q == 0) out[v] = s + __ldg(bd);
}

// ---------------------------------------------------------------------------
extern "C" void kernel_launch(void* const* d_in, const int* in_sizes, int n_in,
                              void* d_out, int out_size) {
    const float* x   = (const float*)d_in[0];
    const int*   ei  = (const int*)d_in[1];
    const float* W1  = (const float*)d_in[2];
    const float* b1  = (const float*)d_in[3];
    const float* W2  = (const float*)d_in[4];
    const float* b2  = (const float*)d_in[5];
    const float* Wd  = (const float*)d_in[6];
    const float* bd  = (const float*)d_in[7];
    float*       out = (float*)d_out;

    k_zero  <<<(NNODES + 255) / 256, 256>>>();
    k_count <<<(NEDGES + 255) / 256, 256>>>(ei);
    k_scan1 <<<NSCANB, 256>>>();
    k_scan23<<<NSCANB, 256>>>();

    k_gemm1<<<(NNODES + 127) / 128, 256>>>(x, W1, ei);   // + fused CSR fill
    k_aggr1<<<(NNODES * 16 + 255) / 256, 256>>>();

    k_layer2<<<(NNODES + 127) / 128, 256>>>(W2, b1);
    k_aggrf <<<(NNODES * 16 + 255) / 256, 256>>>(b2, Wd, bd, out);
}